// round 1
// baseline (speedup 1.0000x reference)
#include <cuda_runtime.h>
#include <cuda_bf16.h>
#include <math.h>

// Problem constants
#define B_  2
#define T_  2048
#define C_  1024
#define H_  16
#define CA_ 64

// Scratch (device globals: allocation-guard safe)
__device__ float g_q[B_ * H_ * T_ * CA_];     // [B,H,T,Ca]
__device__ float g_k[B_ * H_ * T_ * CA_];
__device__ float g_v[B_ * H_ * T_ * CA_];
__device__ float g_y[B_ * T_ * C_];           // y_cat [B,T,C]

// ---------------------------------------------------------------------------
// Fused QKV projection: per head h, Out[b,h,t,a] = sum_c x[b,t,c] * W[h,c,a]
// GEMM: A = x [M=4096, K=1024] row-major; B = W+h*C*Ca [1024, 64] row-major.
// Tile: BM=128, BN=64, BK=16. 256 threads, 8x4 micro-tile.
// blockIdx = (m_tile, head, which of q/k/v)
// ---------------------------------------------------------------------------
#define GBM 128
#define GBN 64
#define GBK 16
#define APAD 4   // As row stride = 132 (16B-aligned, low-conflict)

__global__ __launch_bounds__(256) void qkv_gemm_kernel(
    const float* __restrict__ x,
    const float* __restrict__ wq,
    const float* __restrict__ wk,
    const float* __restrict__ wv)
{
    const int h     = blockIdx.y;
    const int which = blockIdx.z;
    const float* Wmat = (which == 0) ? wq : (which == 1) ? wk : wv;
    float*       Out  = (which == 0) ? g_q : (which == 1) ? g_k : g_v;
    const float* Bmat = Wmat + (size_t)h * C_ * CA_;   // [1024, 64]
    const int m0 = blockIdx.x * GBM;

    __shared__ float As[GBK][GBM + APAD];
    __shared__ float Bs[GBK][GBN];

    const int tid = threadIdx.x;
    const int ty  = tid >> 4;   // 0..15 -> m (x8)
    const int tx  = tid & 15;   // 0..15 -> n (x4)

    float acc[8][4];
#pragma unroll
    for (int i = 0; i < 8; i++)
#pragma unroll
        for (int j = 0; j < 4; j++) acc[i][j] = 0.f;

    for (int kt = 0; kt < C_; kt += GBK) {
        // Load A tile (128x16) as 512 float4, 2 per thread; store transposed.
#pragma unroll
        for (int i = 0; i < 2; i++) {
            int idx = tid + i * 256;           // 0..511
            int row = idx >> 2;
            int c4  = idx & 3;
            float4 v = *(const float4*)&x[(size_t)(m0 + row) * C_ + kt + c4 * 4];
            As[c4 * 4 + 0][row] = v.x;
            As[c4 * 4 + 1][row] = v.y;
            As[c4 * 4 + 2][row] = v.z;
            As[c4 * 4 + 3][row] = v.w;
        }
        // Load B tile (16x64) as 256 float4, 1 per thread.
        {
            int row = tid >> 4;
            int c4  = tid & 15;
            float4 v = *(const float4*)&Bmat[(size_t)(kt + row) * GBN + c4 * 4];
            *(float4*)&Bs[row][c4 * 4] = v;
        }
        __syncthreads();

#pragma unroll
        for (int k = 0; k < GBK; k++) {
            float a[8], b[4];
            float4 a0 = *(const float4*)&As[k][ty * 8];
            float4 a1 = *(const float4*)&As[k][ty * 8 + 4];
            a[0]=a0.x; a[1]=a0.y; a[2]=a0.z; a[3]=a0.w;
            a[4]=a1.x; a[5]=a1.y; a[6]=a1.z; a[7]=a1.w;
            float4 b0 = *(const float4*)&Bs[k][tx * 4];
            b[0]=b0.x; b[1]=b0.y; b[2]=b0.z; b[3]=b0.w;
#pragma unroll
            for (int i = 0; i < 8; i++)
#pragma unroll
                for (int j = 0; j < 4; j++)
                    acc[i][j] += a[i] * b[j];
        }
        __syncthreads();
    }

    // Store: Out[b, h, t, a], m = b*T + t
#pragma unroll
    for (int i = 0; i < 8; i++) {
        int m  = m0 + ty * 8 + i;
        int bb = m >> 11;          // / T_
        int t  = m & (T_ - 1);
        float* dst = Out + (((size_t)(bb * H_ + h) * T_ + t) * CA_) + tx * 4;
        *(float4*)dst = make_float4(acc[i][0], acc[i][1], acc[i][2], acc[i][3]);
    }
}

// ---------------------------------------------------------------------------
// Flash attention (causal), scale applied pre-softmax.
// One block = one (b,h) x 64 query rows. 64 threads, 1 row per thread.
// q and o accumulators in registers; K/V tiles in smem (broadcast reads).
// ---------------------------------------------------------------------------
__global__ void attn_kernel()
{
    const int bh = blockIdx.y;        // b*H + h
    const int qt = blockIdx.x;        // query tile (64 rows)
    const float* Q = g_q + (size_t)bh * T_ * CA_;
    const float* K = g_k + (size_t)bh * T_ * CA_;
    const float* V = g_v + (size_t)bh * T_ * CA_;

    const int r  = threadIdx.x;       // 0..63
    const int qi = qt * 64 + r;

    __shared__ float Ks[64][64];
    __shared__ float Vs[64][64];
    __shared__ float Ss[64][65];      // padded: conflict-free per-row access

    float qreg[64];
#pragma unroll
    for (int a = 0; a < 64; a += 4) {
        float4 v = *(const float4*)&Q[(size_t)qi * CA_ + a];
        qreg[a] = v.x; qreg[a+1] = v.y; qreg[a+2] = v.z; qreg[a+3] = v.w;
    }
    float o[64];
#pragma unroll
    for (int a = 0; a < 64; a++) o[a] = 0.f;

    float mi = -1e30f, li = 0.f;
    const float scale = 0.125f;       // 1/sqrt(64)

    for (int kb = 0; kb <= qt; kb++) {
        // Cooperative tile load: thread r loads K/V row (kb*64 + r).
#pragma unroll
        for (int a = 0; a < 64; a += 4) {
            *(float4*)&Ks[r][a] = *(const float4*)&K[(size_t)(kb * 64 + r) * CA_ + a];
            *(float4*)&Vs[r][a] = *(const float4*)&V[(size_t)(kb * 64 + r) * CA_ + a];
        }
        __syncthreads();

        const int jmax = (kb == qt) ? r : 63;   // causal: key idx <= query idx
        float rowmax = -1e30f;
        for (int j = 0; j <= jmax; j++) {
            float s0 = 0.f, s1 = 0.f, s2 = 0.f, s3 = 0.f;
#pragma unroll
            for (int a = 0; a < 64; a += 4) {
                s0 += qreg[a]     * Ks[j][a];
                s1 += qreg[a + 1] * Ks[j][a + 1];
                s2 += qreg[a + 2] * Ks[j][a + 2];
                s3 += qreg[a + 3] * Ks[j][a + 3];
            }
            float s = ((s0 + s1) + (s2 + s3)) * scale;
            Ss[r][j] = s;
            rowmax = fmaxf(rowmax, s);
        }

        float nm   = fmaxf(mi, rowmax);
        float corr = __expf(mi - nm);
        li *= corr;
#pragma unroll
        for (int a = 0; a < 64; a++) o[a] *= corr;

        for (int j = 0; j <= jmax; j++) {
            float p = __expf(Ss[r][j] - nm);
            li += p;
#pragma unroll
            for (int a = 0; a < 64; a++) o[a] += p * Vs[j][a];
        }
        mi = nm;
        __syncthreads();
    }

    // Write y_cat[b, t=qi, h*64 + a]
    const int bb = bh / H_;
    const int h  = bh % H_;
    const float inv = 1.f / li;
    float* dst = g_y + ((size_t)bb * T_ + qi) * C_ + h * CA_;
#pragma unroll
    for (int a = 0; a < 64; a += 4) {
        *(float4*)&dst[a] = make_float4(o[a] * inv, o[a+1] * inv, o[a+2] * inv, o[a+3] * inv);
    }
}

// ---------------------------------------------------------------------------
// Output projection: out[m, n] = sum_c y_cat[m, c] * w_o[c, n]
// Same tile shape as the QKV GEMM; N = 1024 tiled by 64.
// ---------------------------------------------------------------------------
__global__ __launch_bounds__(256) void out_gemm_kernel(
    const float* __restrict__ wo,
    float* __restrict__ out)
{
    const int m0 = blockIdx.x * GBM;
    const int n0 = blockIdx.y * GBN;

    __shared__ float As[GBK][GBM + APAD];
    __shared__ float Bs[GBK][GBN];

    const int tid = threadIdx.x;
    const int ty  = tid >> 4;
    const int tx  = tid & 15;

    float acc[8][4];
#pragma unroll
    for (int i = 0; i < 8; i++)
#pragma unroll
        for (int j = 0; j < 4; j++) acc[i][j] = 0.f;

    for (int kt = 0; kt < C_; kt += GBK) {
#pragma unroll
        for (int i = 0; i < 2; i++) {
            int idx = tid + i * 256;
            int row = idx >> 2;
            int c4  = idx & 3;
            float4 v = *(const float4*)&g_y[(size_t)(m0 + row) * C_ + kt + c4 * 4];
            As[c4 * 4 + 0][row] = v.x;
            As[c4 * 4 + 1][row] = v.y;
            As[c4 * 4 + 2][row] = v.z;
            As[c4 * 4 + 3][row] = v.w;
        }
        {
            int row = tid >> 4;
            int c4  = tid & 15;
            float4 v = *(const float4*)&wo[(size_t)(kt + row) * C_ + n0 + c4 * 4];
            *(float4*)&Bs[row][c4 * 4] = v;
        }
        __syncthreads();

#pragma unroll
        for (int k = 0; k < GBK; k++) {
            float a[8], b[4];
            float4 a0 = *(const float4*)&As[k][ty * 8];
            float4 a1 = *(const float4*)&As[k][ty * 8 + 4];
            a[0]=a0.x; a[1]=a0.y; a[2]=a0.z; a[3]=a0.w;
            a[4]=a1.x; a[5]=a1.y; a[6]=a1.z; a[7]=a1.w;
            float4 b0 = *(const float4*)&Bs[k][tx * 4];
            b[0]=b0.x; b[1]=b0.y; b[2]=b0.z; b[3]=b0.w;
#pragma unroll
            for (int i = 0; i < 8; i++)
#pragma unroll
                for (int j = 0; j < 4; j++)
                    acc[i][j] += a[i] * b[j];
        }
        __syncthreads();
    }

#pragma unroll
    for (int i = 0; i < 8; i++) {
        int m = m0 + ty * 8 + i;
        float* dst = out + (size_t)m * C_ + n0 + tx * 4;
        *(float4*)dst = make_float4(acc[i][0], acc[i][1], acc[i][2], acc[i][3]);
    }
}

// ---------------------------------------------------------------------------
extern "C" void kernel_launch(void* const* d_in, const int* in_sizes, int n_in,
                              void* d_out, int out_size)
{
    const float* x   = (const float*)d_in[0];
    const float* w_q = (const float*)d_in[1];
    const float* w_k = (const float*)d_in[2];
    const float* w_v = (const float*)d_in[3];
    const float* w_o = (const float*)d_in[4];
    float* out = (float*)d_out;

    // 1) QKV projections: grid (M/128, H, 3)
    dim3 g1((B_ * T_) / GBM, H_, 3);
    qkv_gemm_kernel<<<g1, 256>>>(x, w_q, w_k, w_v);

    // 2) Causal flash attention: grid (T/64 q-tiles, B*H)
    dim3 g2(T_ / 64, B_ * H_);
    attn_kernel<<<g2, 64>>>();

    // 3) Output projection: grid (M/128, C/64)
    dim3 g3((B_ * T_) / GBM, C_ / GBN);
    out_gemm_kernel<<<g3, 256>>>(w_o, out);
}

// round 2
// speedup vs baseline: 1.2925x; 1.2925x over previous
#include <cuda_runtime.h>
#include <cuda_bf16.h>
#include <math.h>

// Problem constants
#define B_  2
#define T_  2048
#define C_  1024
#define H_  16
#define CA_ 64

// Scratch (device globals: allocation-guard safe)
__device__ float g_qT[B_ * H_ * CA_ * T_];    // Q^T [bh, a, t], scale folded
__device__ float g_kT[B_ * H_ * CA_ * T_];    // K^T [bh, a, t]
__device__ float g_v [B_ * H_ * T_ * CA_];    // V   [bh, t, a]
__device__ float g_y [B_ * T_ * C_];          // y_cat [B,T,C]

// ---------------------------------------------------------------------------
// Fused QKV projection, 8x8 micro-tile, 128 threads, tile 128(M) x 64(N) x 16(K)
// Q/K stored transposed [bh, a, t]; scale 0.125 folded into Q. V natural.
// ---------------------------------------------------------------------------
__global__ __launch_bounds__(128) void qkv_gemm_kernel(
    const float* __restrict__ x,
    const float* __restrict__ wq,
    const float* __restrict__ wk,
    const float* __restrict__ wv)
{
    const int h     = blockIdx.y;
    const int which = blockIdx.z;
    const float* Wmat = (which == 0) ? wq : (which == 1) ? wk : wv;
    const float* Bmat = Wmat + (size_t)h * C_ * CA_;   // [1024, 64]
    const int m0 = blockIdx.x * 128;

    __shared__ float As[16][132];   // [k][m]
    __shared__ float Bs[16][68];    // [k][n]

    const int tid = threadIdx.x;
    const int ty  = tid >> 3;   // 0..15 -> m (x8)
    const int tx  = tid & 7;    // 0..7  -> n (x8)

    float acc[8][8];
#pragma unroll
    for (int i = 0; i < 8; i++)
#pragma unroll
        for (int j = 0; j < 8; j++) acc[i][j] = 0.f;

    for (int kt = 0; kt < C_; kt += 16) {
        // A tile 128x16 = 512 float4, 4/thread, stored transposed
#pragma unroll
        for (int i = 0; i < 4; i++) {
            int idx = tid + i * 128;       // 0..511
            int row = idx >> 2;
            int c4  = idx & 3;
            float4 v = *(const float4*)&x[(size_t)(m0 + row) * C_ + kt + c4 * 4];
            As[c4 * 4 + 0][row] = v.x;
            As[c4 * 4 + 1][row] = v.y;
            As[c4 * 4 + 2][row] = v.z;
            As[c4 * 4 + 3][row] = v.w;
        }
        // B tile 16x64 = 256 float4, 2/thread
#pragma unroll
        for (int i = 0; i < 2; i++) {
            int idx = tid + i * 128;       // 0..255
            int row = idx >> 4;
            int c4  = idx & 15;
            *(float4*)&Bs[row][c4 * 4] =
                *(const float4*)&Bmat[(size_t)(kt + row) * CA_ + c4 * 4];
        }
        __syncthreads();

#pragma unroll
        for (int k = 0; k < 16; k++) {
            float a[8], b[8];
            float4 a0 = *(const float4*)&As[k][ty * 8];
            float4 a1 = *(const float4*)&As[k][ty * 8 + 4];
            a[0]=a0.x; a[1]=a0.y; a[2]=a0.z; a[3]=a0.w;
            a[4]=a1.x; a[5]=a1.y; a[6]=a1.z; a[7]=a1.w;
            float4 b0 = *(const float4*)&Bs[k][tx * 8];
            float4 b1 = *(const float4*)&Bs[k][tx * 8 + 4];
            b[0]=b0.x; b[1]=b0.y; b[2]=b0.z; b[3]=b0.w;
            b[4]=b1.x; b[5]=b1.y; b[6]=b1.z; b[7]=b1.w;
#pragma unroll
            for (int i = 0; i < 8; i++)
#pragma unroll
                for (int j = 0; j < 8; j++)
                    acc[i][j] += a[i] * b[j];
        }
        __syncthreads();
    }

    if (which == 2) {
        // V natural [bh, t, a]
#pragma unroll
        for (int i = 0; i < 8; i++) {
            int m  = m0 + ty * 8 + i;
            int bb = m >> 11;
            int t  = m & (T_ - 1);
            float* dst = g_v + (((size_t)(bb * H_ + h) * T_ + t) * CA_) + tx * 8;
            *(float4*)&dst[0] = make_float4(acc[i][0], acc[i][1], acc[i][2], acc[i][3]);
            *(float4*)&dst[4] = make_float4(acc[i][4], acc[i][5], acc[i][6], acc[i][7]);
        }
    } else {
        // Q^T / K^T [bh, a, t]; fold softmax scale into Q
        float* Out = (which == 0) ? g_qT : g_kT;
        const float sc = (which == 0) ? 0.125f : 1.0f;
#pragma unroll
        for (int i = 0; i < 8; i++) {
            int m  = m0 + ty * 8 + i;
            int bb = m >> 11;
            int t  = m & (T_ - 1);
            size_t base = (size_t)(bb * H_ + h) * CA_ * T_;
#pragma unroll
            for (int j = 0; j < 8; j++) {
                int a = tx * 8 + j;
                Out[base + (size_t)a * T_ + t] = acc[i][j] * sc;
            }
        }
    }
}

// ---------------------------------------------------------------------------
// Flash attention (causal), GEMM-tiled: 128 queries x 64-key tiles.
// 128 threads, 8x8 fragments for both S=Q@K^T and O+=P@V.
// Dynamic smem: Qs[64][132] (a-major), Ks[64][68] (a-major), Vs[64][68],
//               Ps[64][132] (j-major = P^T). 102400 bytes -> 2 CTAs/SM.
// ---------------------------------------------------------------------------
#define AQ 128
#define AKT 64
#define ATTN_SMEM_BYTES ((64*132 + 64*68 + 64*68 + 64*132) * 4)

__global__ __launch_bounds__(128) void attn_kernel()
{
    extern __shared__ float smf[];
    float* Qs = smf;                  // [64][132]
    float* Ks = Qs + 64 * 132;        // [64][68]
    float* Vs = Ks + 64 * 68;         // [64][68]
    float* Ps = Vs + 64 * 68;         // [64][132]

    const int bh = blockIdx.y;
    const int qt = blockIdx.x;
    const int q0 = qt * AQ;
    const float* QT = g_qT + (size_t)bh * CA_ * T_;
    const float* KT = g_kT + (size_t)bh * CA_ * T_;
    const float* V  = g_v  + (size_t)bh * T_ * CA_;

    const int tid = threadIdx.x;
    const int ty  = tid >> 3;   // 0..15 -> q rows (x8)
    const int tx  = tid & 7;    // 0..7  -> cols (x8)

    // Load Q tile (a-major): 64 x 128 = 2048 float4, 16/thread
#pragma unroll
    for (int i = 0; i < 16; i++) {
        int idx = tid + i * 128;
        int a   = idx >> 5;
        int c4  = idx & 31;
        *(float4*)&Qs[a * 132 + c4 * 4] =
            *(const float4*)&QT[(size_t)a * T_ + q0 + c4 * 4];
    }

    float m_[8], l_[8], acc2[8][8];
#pragma unroll
    for (int i = 0; i < 8; i++) {
        m_[i] = -1e30f; l_[i] = 0.f;
#pragma unroll
        for (int j = 0; j < 8; j++) acc2[i][j] = 0.f;
    }

    const int ktiles = 2 * qt + 2;
    for (int kb = 0; kb < ktiles; kb++) {
        const int k0 = kb * AKT;
        __syncthreads();
        // K^T tile (a-major) and V tile (j-major): 1024 float4 each, 8/thread
#pragma unroll
        for (int i = 0; i < 8; i++) {
            int idx = tid + i * 128;
            int r   = idx >> 4;
            int c4  = idx & 15;
            *(float4*)&Ks[r * 68 + c4 * 4] =
                *(const float4*)&KT[(size_t)r * T_ + k0 + c4 * 4];
            *(float4*)&Vs[r * 68 + c4 * 4] =
                *(const float4*)&V[(size_t)(k0 + r) * CA_ + c4 * 4];
        }
        __syncthreads();

        // S = Q @ K^T (scale already folded into Q)
        float acc[8][8];
#pragma unroll
        for (int i = 0; i < 8; i++)
#pragma unroll
            for (int j = 0; j < 8; j++) acc[i][j] = 0.f;

#pragma unroll 2
        for (int a = 0; a < 64; a++) {
            float qa[8], kk[8];
            float4 v0 = *(const float4*)&Qs[a * 132 + ty * 8];
            float4 v1 = *(const float4*)&Qs[a * 132 + ty * 8 + 4];
            qa[0]=v0.x; qa[1]=v0.y; qa[2]=v0.z; qa[3]=v0.w;
            qa[4]=v1.x; qa[5]=v1.y; qa[6]=v1.z; qa[7]=v1.w;
            float4 w0 = *(const float4*)&Ks[a * 68 + tx * 8];
            float4 w1 = *(const float4*)&Ks[a * 68 + tx * 8 + 4];
            kk[0]=w0.x; kk[1]=w0.y; kk[2]=w0.z; kk[3]=w0.w;
            kk[4]=w1.x; kk[5]=w1.y; kk[6]=w1.z; kk[7]=w1.w;
#pragma unroll
            for (int i = 0; i < 8; i++)
#pragma unroll
                for (int j = 0; j < 8; j++)
                    acc[i][j] += qa[i] * kk[j];
        }

        // Causal mask (only the last two tiles can cross the diagonal)
        if (kb >= 2 * qt) {
#pragma unroll
            for (int i = 0; i < 8; i++) {
                int qg = q0 + ty * 8 + i;
#pragma unroll
                for (int j = 0; j < 8; j++) {
                    int jg = k0 + tx * 8 + j;
                    if (jg > qg) acc[i][j] = -1e30f;
                }
            }
        }

        // Online softmax per row; write P^T into Ps
#pragma unroll
        for (int i = 0; i < 8; i++) {
            float rmax = acc[i][0];
#pragma unroll
            for (int j = 1; j < 8; j++) rmax = fmaxf(rmax, acc[i][j]);
            rmax = fmaxf(rmax, __shfl_xor_sync(0xffffffffu, rmax, 1));
            rmax = fmaxf(rmax, __shfl_xor_sync(0xffffffffu, rmax, 2));
            rmax = fmaxf(rmax, __shfl_xor_sync(0xffffffffu, rmax, 4));
            float mnew = fmaxf(m_[i], rmax);
            float corr = __expf(m_[i] - mnew);
            float ps = 0.f;
#pragma unroll
            for (int j = 0; j < 8; j++) {
                float p = __expf(acc[i][j] - mnew);
                Ps[(tx * 8 + j) * 132 + ty * 8 + i] = p;
                ps += p;
            }
            ps += __shfl_xor_sync(0xffffffffu, ps, 1);
            ps += __shfl_xor_sync(0xffffffffu, ps, 2);
            ps += __shfl_xor_sync(0xffffffffu, ps, 4);
            l_[i] = l_[i] * corr + ps;
            m_[i] = mnew;
#pragma unroll
            for (int j = 0; j < 8; j++) acc2[i][j] *= corr;
        }
        __syncthreads();

        // O += P @ V  (reduction over j; P^T is a-operand, V is b-operand)
#pragma unroll 2
        for (int j = 0; j < 64; j++) {
            float pa[8], va[8];
            float4 p0 = *(const float4*)&Ps[j * 132 + ty * 8];
            float4 p1 = *(const float4*)&Ps[j * 132 + ty * 8 + 4];
            pa[0]=p0.x; pa[1]=p0.y; pa[2]=p0.z; pa[3]=p0.w;
            pa[4]=p1.x; pa[5]=p1.y; pa[6]=p1.z; pa[7]=p1.w;
            float4 u0 = *(const float4*)&Vs[j * 68 + tx * 8];
            float4 u1 = *(const float4*)&Vs[j * 68 + tx * 8 + 4];
            va[0]=u0.x; va[1]=u0.y; va[2]=u0.z; va[3]=u0.w;
            va[4]=u1.x; va[5]=u1.y; va[6]=u1.z; va[7]=u1.w;
#pragma unroll
            for (int i = 0; i < 8; i++)
#pragma unroll
                for (int jj = 0; jj < 8; jj++)
                    acc2[i][jj] += pa[i] * va[jj];
        }
    }

    // Epilogue: y_cat[b, t, h*64 + a] = O / l
    const int bb = bh >> 4;
    const int h  = bh & 15;
#pragma unroll
    for (int i = 0; i < 8; i++) {
        float inv = 1.f / l_[i];
        int t = q0 + ty * 8 + i;
        float* dst = g_y + ((size_t)bb * T_ + t) * C_ + h * CA_ + tx * 8;
        *(float4*)&dst[0] = make_float4(acc2[i][0]*inv, acc2[i][1]*inv, acc2[i][2]*inv, acc2[i][3]*inv);
        *(float4*)&dst[4] = make_float4(acc2[i][4]*inv, acc2[i][5]*inv, acc2[i][6]*inv, acc2[i][7]*inv);
    }
}

// ---------------------------------------------------------------------------
// Output projection, 8x8 micro-tile, 128 threads, tile 128x64x16
// ---------------------------------------------------------------------------
__global__ __launch_bounds__(128) void out_gemm_kernel(
    const float* __restrict__ wo,
    float* __restrict__ out)
{
    const int m0 = blockIdx.x * 128;
    const int n0 = blockIdx.y * 64;

    __shared__ float As[16][132];
    __shared__ float Bs[16][68];

    const int tid = threadIdx.x;
    const int ty  = tid >> 3;
    const int tx  = tid & 7;

    float acc[8][8];
#pragma unroll
    for (int i = 0; i < 8; i++)
#pragma unroll
        for (int j = 0; j < 8; j++) acc[i][j] = 0.f;

    for (int kt = 0; kt < C_; kt += 16) {
#pragma unroll
        for (int i = 0; i < 4; i++) {
            int idx = tid + i * 128;
            int row = idx >> 2;
            int c4  = idx & 3;
            float4 v = *(const float4*)&g_y[(size_t)(m0 + row) * C_ + kt + c4 * 4];
            As[c4 * 4 + 0][row] = v.x;
            As[c4 * 4 + 1][row] = v.y;
            As[c4 * 4 + 2][row] = v.z;
            As[c4 * 4 + 3][row] = v.w;
        }
#pragma unroll
        for (int i = 0; i < 2; i++) {
            int idx = tid + i * 128;
            int row = idx >> 4;
            int c4  = idx & 15;
            *(float4*)&Bs[row][c4 * 4] =
                *(const float4*)&wo[(size_t)(kt + row) * C_ + n0 + c4 * 4];
        }
        __syncthreads();

#pragma unroll
        for (int k = 0; k < 16; k++) {
            float a[8], b[8];
            float4 a0 = *(const float4*)&As[k][ty * 8];
            float4 a1 = *(const float4*)&As[k][ty * 8 + 4];
            a[0]=a0.x; a[1]=a0.y; a[2]=a0.z; a[3]=a0.w;
            a[4]=a1.x; a[5]=a1.y; a[6]=a1.z; a[7]=a1.w;
            float4 b0 = *(const float4*)&Bs[k][tx * 8];
            float4 b1 = *(const float4*)&Bs[k][tx * 8 + 4];
            b[0]=b0.x; b[1]=b0.y; b[2]=b0.z; b[3]=b0.w;
            b[4]=b1.x; b[5]=b1.y; b[6]=b1.z; b[7]=b1.w;
#pragma unroll
            for (int i = 0; i < 8; i++)
#pragma unroll
                for (int j = 0; j < 8; j++)
                    acc[i][j] += a[i] * b[j];
        }
        __syncthreads();
    }

#pragma unroll
    for (int i = 0; i < 8; i++) {
        int m = m0 + ty * 8 + i;
        float* dst = out + (size_t)m * C_ + n0 + tx * 8;
        *(float4*)&dst[0] = make_float4(acc[i][0], acc[i][1], acc[i][2], acc[i][3]);
        *(float4*)&dst[4] = make_float4(acc[i][4], acc[i][5], acc[i][6], acc[i][7]);
    }
}

// ---------------------------------------------------------------------------
extern "C" void kernel_launch(void* const* d_in, const int* in_sizes, int n_in,
                              void* d_out, int out_size)
{
    const float* x   = (const float*)d_in[0];
    const float* w_q = (const float*)d_in[1];
    const float* w_k = (const float*)d_in[2];
    const float* w_v = (const float*)d_in[3];
    const float* w_o = (const float*)d_in[4];
    float* out = (float*)d_out;

    cudaFuncSetAttribute(attn_kernel,
                         cudaFuncAttributeMaxDynamicSharedMemorySize,
                         ATTN_SMEM_BYTES);

    // 1) QKV projections: grid (M/128, H, 3)
    dim3 g1((B_ * T_) / 128, H_, 3);
    qkv_gemm_kernel<<<g1, 128>>>(x, w_q, w_k, w_v);

    // 2) Causal flash attention: grid (T/128 q-tiles, B*H)
    dim3 g2(T_ / AQ, B_ * H_);
    attn_kernel<<<g2, 128, ATTN_SMEM_BYTES>>>();

    // 3) Output projection: grid (M/128, C/64)
    dim3 g3((B_ * T_) / 128, C_ / 64);
    out_gemm_kernel<<<g3, 128>>>(w_o, out);
}

// round 5
// speedup vs baseline: 2.8409x; 2.1979x over previous
#include <cuda_runtime.h>
#include <cuda_bf16.h>
#include <math.h>
#include <stdint.h>

// Problem constants
#define B_  2
#define T_  2048
#define C_  1024
#define H_  16
#define CA_ 64
#define BH_ (B_*H_)
#define M_TOT (B_*T_)   // 4096

// ---------------------------------------------------------------------------
// bf16 hi/lo split scratch (device globals: allocation-guard safe)
// ---------------------------------------------------------------------------
__device__ __align__(128) __nv_bfloat16 g_xh[M_TOT*C_],  g_xl[M_TOT*C_];
__device__ __align__(128) __nv_bfloat16 g_wTh[3*H_*CA_*C_], g_wTl[3*H_*CA_*C_];
__device__ __align__(128) __nv_bfloat16 g_woTh[C_*C_],   g_woTl[C_*C_];
__device__ __align__(128) __nv_bfloat16 g_qh[BH_*T_*CA_], g_ql[BH_*T_*CA_];
__device__ __align__(128) __nv_bfloat16 g_kh[BH_*T_*CA_], g_kl[BH_*T_*CA_];
__device__ __align__(128) __nv_bfloat16 g_vTh[BH_*CA_*T_], g_vTl[BH_*CA_*T_];
__device__ __align__(128) __nv_bfloat16 g_yh[M_TOT*C_],  g_yl[M_TOT*C_];

// ---------------------------------------------------------------------------
// helpers
// ---------------------------------------------------------------------------
__device__ __forceinline__ uint32_t smem_u32(const void* p) {
    uint32_t a;
    asm("{ .reg .u64 t; cvta.to.shared.u64 t, %1; cvt.u32.u64 %0, t; }"
        : "=r"(a) : "l"(p));
    return a;
}

#define LDM_X4(regs, addr) \
    asm volatile("ldmatrix.sync.aligned.m8n8.x4.shared.b16 {%0,%1,%2,%3}, [%4];" \
        : "=r"((regs)[0]),"=r"((regs)[1]),"=r"((regs)[2]),"=r"((regs)[3]) : "r"(addr))

__device__ __forceinline__ void mma16816(float* d, const uint32_t* a, const uint32_t* b) {
    asm volatile("mma.sync.aligned.m16n8k16.row.col.f32.bf16.bf16.f32 "
        "{%0,%1,%2,%3}, {%4,%5,%6,%7}, {%8,%9}, {%0,%1,%2,%3};"
        : "+f"(d[0]),"+f"(d[1]),"+f"(d[2]),"+f"(d[3])
        : "r"(a[0]),"r"(a[1]),"r"(a[2]),"r"(a[3]), "r"(b[0]),"r"(b[1]));
}

__device__ __forceinline__ void split2(float v, __nv_bfloat16& h, __nv_bfloat16& l) {
    h = __float2bfloat16(v);
    l = __float2bfloat16(v - __bfloat162float(h));
}
union Pack8 { __nv_bfloat16 b[8]; uint4 u; };
union Pack2 { __nv_bfloat16 b[2]; uint32_t u; };

// bf16 tile row stride: 72 elems = 144 bytes (conflict-free for ldmatrix & STS)
#define SBF   72
#define SBFB  144

// ---------------------------------------------------------------------------
// Core warp-tile MMA over one K=64 chunk, 3-term hi/lo split.
// A tile: [rows][64] bf16 stride 72 (row-major, k contiguous)
// B tile: [n][64]    bf16 stride 72 (k contiguous = col-major for mma)
// Warp computes 32(M) x 32(N): D[2 mi][4 nf][4]
// ---------------------------------------------------------------------------
__device__ __forceinline__ void mma_tile_k64(
    float D[2][4][4],
    uint32_t aH, uint32_t aL, uint32_t bH, uint32_t bL,
    int warp_m, int warp_n, int lane)
{
    const uint32_t abyte = (uint32_t)(warp_m*32 + (lane & 15)) * SBFB + ((lane >> 4) * 16);
    const uint32_t bbyte = (uint32_t)(warp_n*32 + (lane & 7) + (((lane >> 4) & 1) * 8)) * SBFB
                         + (((lane >> 3) & 1) * 16);
#pragma unroll
    for (int ks = 0; ks < 4; ks++) {
        uint32_t ah[2][4], al[2][4], bh[2][4], bl[2][4];
#pragma unroll
        for (int mi = 0; mi < 2; mi++) {
            LDM_X4(ah[mi], aH + abyte + mi*16*SBFB + ks*32);
            LDM_X4(al[mi], aL + abyte + mi*16*SBFB + ks*32);
        }
#pragma unroll
        for (int np = 0; np < 2; np++) {
            LDM_X4(bh[np], bH + bbyte + np*16*SBFB + ks*32);
            LDM_X4(bl[np], bL + bbyte + np*16*SBFB + ks*32);
        }
#pragma unroll
        for (int mi = 0; mi < 2; mi++)
#pragma unroll
        for (int np = 0; np < 2; np++) {
            mma16816(D[mi][2*np],   ah[mi], &bh[np][0]);
            mma16816(D[mi][2*np],   ah[mi], &bl[np][0]);
            mma16816(D[mi][2*np],   al[mi], &bh[np][0]);
            mma16816(D[mi][2*np+1], ah[mi], &bh[np][2]);
            mma16816(D[mi][2*np+1], ah[mi], &bl[np][2]);
            mma16816(D[mi][2*np+1], al[mi], &bh[np][2]);
        }
    }
}

// ---------------------------------------------------------------------------
// Prep 1: elementwise split of x
// ---------------------------------------------------------------------------
__global__ __launch_bounds__(128) void split_x_kernel(const float* __restrict__ x) {
    size_t i8 = ((size_t)blockIdx.x * 128 + threadIdx.x) * 8;
    float4 v0 = *(const float4*)&x[i8];
    float4 v1 = *(const float4*)&x[i8 + 4];
    float v[8] = {v0.x, v0.y, v0.z, v0.w, v1.x, v1.y, v1.z, v1.w};
    Pack8 h, l;
#pragma unroll
    for (int e = 0; e < 8; e++) split2(v[e], h.b[e], l.b[e]);
    *(uint4*)&g_xh[i8] = h.u;
    *(uint4*)&g_xl[i8] = l.u;
}

// ---------------------------------------------------------------------------
// Prep 2: transpose + split weights.
//   y in [0,48):  w_{q,k,v}[h][c][a]  ->  g_wT*[which][h][a][c]
//   y in [48,64): w_o[c][n]           ->  g_woT*[n][c]
// ---------------------------------------------------------------------------
__global__ __launch_bounds__(128) void tsplit_kernel(
    const float* __restrict__ wq, const float* __restrict__ wk,
    const float* __restrict__ wv, const float* __restrict__ wo) {
    __shared__ float ts[64 * 65];
    const int tid = threadIdx.x;
    const int c0  = blockIdx.x * 64;
    const int y   = blockIdx.y;

    const float* src; int sstride, coloff;
    __nv_bfloat16 *dsth, *dstl;
    if (y < 48) {
        int which = y >> 4, h = y & 15;
        const float* w = (which == 0) ? wq : (which == 1) ? wk : wv;
        src = w + (size_t)h * C_ * CA_;
        sstride = CA_; coloff = 0;
        dsth = g_wTh + (size_t)(which * H_ + h) * CA_ * C_;
        dstl = g_wTl + (size_t)(which * H_ + h) * CA_ * C_;
    } else {
        int nt = y - 48;
        src = wo; sstride = C_; coloff = nt * 64;
        dsth = g_woTh + (size_t)(nt * 64) * C_;
        dstl = g_woTl + (size_t)(nt * 64) * C_;
    }

#pragma unroll
    for (int i = 0; i < 8; i++) {
        int idx = tid + i * 128;
        int r = idx >> 4, q = idx & 15;
        float4 v = *(const float4*)&src[(size_t)(c0 + r) * sstride + coloff + q * 4];
        ts[r * 65 + q * 4 + 0] = v.x;
        ts[r * 65 + q * 4 + 1] = v.y;
        ts[r * 65 + q * 4 + 2] = v.z;
        ts[r * 65 + q * 4 + 3] = v.w;
    }
    __syncthreads();

#pragma unroll
    for (int i = 0; i < 4; i++) {
        int idx = tid + i * 128;
        int a = idx >> 3, c8 = idx & 7;
        Pack8 h, l;
#pragma unroll
        for (int j = 0; j < 8; j++)
            split2(ts[(c8 * 8 + j) * 65 + a], h.b[j], l.b[j]);
        size_t o = (size_t)a * C_ + c0 + c8 * 8;
        *(uint4*)&dsth[o] = h.u;
        *(uint4*)&dstl[o] = l.u;
    }
}

// ---------------------------------------------------------------------------
// smem layout for GEMM kernels (qkv / out-proj), K chunk = 64
// ---------------------------------------------------------------------------
#define GOF_AH 0
#define GOF_AL (128*SBFB)            // 18432
#define GOF_BH (2*128*SBFB)          // 36864
#define GOF_BL (2*128*SBFB + 64*SBFB)
#define GEMM_SMEM (2*128*SBFB + 2*64*SBFB)   // 55296

// ---------------------------------------------------------------------------
// QKV projection: Out[b,h,t,a] = sum_c x * W ; grid (32, H, 3), 256 thr
// ---------------------------------------------------------------------------
__global__ __launch_bounds__(256) void qkv_mma_kernel() {
    extern __shared__ char sm[];
    const uint32_t smb = smem_u32(sm);
    const int tid = threadIdx.x, lane = tid & 31, wid = tid >> 5;
    const int wm = wid >> 1, wn = wid & 1;
    const int m0 = blockIdx.x * 128;
    const int h  = blockIdx.y;
    const int which = blockIdx.z;

    const __nv_bfloat16* bh_src = g_wTh + (size_t)(which * H_ + h) * CA_ * C_;
    const __nv_bfloat16* bl_src = g_wTl + (size_t)(which * H_ + h) * CA_ * C_;

    float D[2][4][4];
#pragma unroll
    for (int a = 0; a < 2; a++)
#pragma unroll
        for (int b = 0; b < 4; b++)
#pragma unroll
            for (int c = 0; c < 4; c++) D[a][b][c] = 0.f;

    for (int ck = 0; ck < 16; ck++) {
        const int kt = ck * 64;
        // A: 128 rows x 64 cols, 1024 16B chunks per buffer
#pragma unroll
        for (int i = 0; i < 4; i++) {
            int idx = tid + i * 256;
            int r = idx >> 3, q = idx & 7;
            uint32_t so = r * SBFB + q * 16;
            size_t go = (size_t)(m0 + r) * C_ + kt + q * 8;
            *(uint4*)(sm + GOF_AH + so) = *(const uint4*)&g_xh[go];
            *(uint4*)(sm + GOF_AL + so) = *(const uint4*)&g_xl[go];
        }
        // B: 64 rows x 64 cols, 512 chunks per buffer
#pragma unroll
        for (int i = 0; i < 2; i++) {
            int idx = tid + i * 256;
            int r = idx >> 3, q = idx & 7;
            uint32_t so = r * SBFB + q * 16;
            size_t go = (size_t)r * C_ + kt + q * 8;
            *(uint4*)(sm + GOF_BH + so) = *(const uint4*)&bh_src[go];
            *(uint4*)(sm + GOF_BL + so) = *(const uint4*)&bl_src[go];
        }
        __syncthreads();
        mma_tile_k64(D, smb + GOF_AH, smb + GOF_AL, smb + GOF_BH, smb + GOF_BL,
                     wm, wn, lane);
        __syncthreads();
    }

    const int bb = m0 >> 11;          // batch of this m-tile (tile never spans)
    const int m0t = m0 & (T_ - 1);

    if (which != 2) {
        const float sc = (which == 0) ? 0.125f : 1.0f;
        __nv_bfloat16* dh = (which == 0) ? g_qh : g_kh;
        __nv_bfloat16* dl = (which == 0) ? g_ql : g_kl;
        size_t hbase = (size_t)(bb * H_ + h) * T_ * CA_;
#pragma unroll
        for (int mi = 0; mi < 2; mi++) {
            int r0 = wm * 32 + mi * 16 + (lane >> 2);
#pragma unroll
            for (int half = 0; half < 2; half++) {
                int row = r0 + half * 8;
                size_t rb = hbase + (size_t)(m0t + row) * CA_;
#pragma unroll
                for (int nf = 0; nf < 4; nf++) {
                    int col = wn * 32 + nf * 8 + 2 * (lane & 3);
                    float v0 = D[mi][nf][half * 2 + 0] * sc;
                    float v1 = D[mi][nf][half * 2 + 1] * sc;
                    Pack2 ph, pl;
                    split2(v0, ph.b[0], pl.b[0]);
                    split2(v1, ph.b[1], pl.b[1]);
                    *(uint32_t*)&dh[rb + col] = ph.u;
                    *(uint32_t*)&dl[rb + col] = pl.u;
                }
            }
        }
    } else {
        // V: stage fp32 tile in smem (reuse A region), then transposed store
        float* Vs = (float*)sm;       // [128][68]
#pragma unroll
        for (int mi = 0; mi < 2; mi++) {
            int r0 = wm * 32 + mi * 16 + (lane >> 2);
#pragma unroll
            for (int nf = 0; nf < 4; nf++) {
                int col = wn * 32 + nf * 8 + 2 * (lane & 3);
                Vs[(r0    ) * 68 + col    ] = D[mi][nf][0];
                Vs[(r0    ) * 68 + col + 1] = D[mi][nf][1];
                Vs[(r0 + 8) * 68 + col    ] = D[mi][nf][2];
                Vs[(r0 + 8) * 68 + col + 1] = D[mi][nf][3];
            }
        }
        __syncthreads();
        const int a = tid & 63, part = tid >> 6;     // part 0..3 -> 32 t each
        size_t base = ((size_t)(bb * H_ + h) * CA_ + a) * T_ + m0t + part * 32;
#pragma unroll
        for (int j8 = 0; j8 < 4; j8++) {
            Pack8 hh, ll;
#pragma unroll
            for (int e = 0; e < 8; e++)
                split2(Vs[(part * 32 + j8 * 8 + e) * 68 + a], hh.b[e], ll.b[e]);
            *(uint4*)&g_vTh[base + j8 * 8] = hh.u;
            *(uint4*)&g_vTl[base + j8 * 8] = ll.u;
        }
    }
}

// ---------------------------------------------------------------------------
// Flash attention: 128 q-rows x 64-key tiles, 256 thr, mma.sync
// ---------------------------------------------------------------------------
#define AOF_QH 0
#define AOF_QL (128*SBFB)
#define AOF_KH (2*128*SBFB)                 // 36864
#define AOF_KL (AOF_KH + 64*SBFB)
#define AOF_VH (AOF_KH + 2*64*SBFB)
#define AOF_VL (AOF_KH + 3*64*SBFB)
#define AOF_S  (AOF_KH + 4*64*SBFB)         // 73728, f32 [128][65]
#define AOF_PH (AOF_S + 128*65*4)           // 107008
#define AOF_PL (AOF_PH + 128*SBFB)
#define AOF_CR (AOF_PL + 128*SBFB)          // 143872, f32 [128]
#define ATT_SMEM (AOF_CR + 512)             // 144384

__global__ __launch_bounds__(256) void attn_mma_kernel() {
    extern __shared__ char sm[];
    const uint32_t smb = smem_u32(sm);
    float* S    = (float*)(sm + AOF_S);
    float* corr_sm = (float*)(sm + AOF_CR);
    const int tid = threadIdx.x, lane = tid & 31, wid = tid >> 5;
    const int wm = wid >> 1, wn = wid & 1;
    const int qt = blockIdx.x, bh = blockIdx.y;
    const int q0 = qt * 128;

    // Stage Q (persistent)
#pragma unroll
    for (int i = 0; i < 4; i++) {
        int idx = tid + i * 256;
        int r = idx >> 3, q = idx & 7;
        uint32_t so = r * SBFB + q * 16;
        size_t go = ((size_t)bh * T_ + q0 + r) * CA_ + q * 8;
        *(uint4*)(sm + AOF_QH + so) = *(const uint4*)&g_qh[go];
        *(uint4*)(sm + AOF_QL + so) = *(const uint4*)&g_ql[go];
    }

    float DO[2][4][4];
#pragma unroll
    for (int a = 0; a < 2; a++)
#pragma unroll
        for (int b = 0; b < 4; b++)
#pragma unroll
            for (int c = 0; c < 4; c++) DO[a][b][c] = 0.f;
    float mi_s = -1e30f, li = 0.f;     // softmax state for row tid (tid<128)

    const int ktiles = 2 * qt + 2;
    for (int kb = 0; kb < ktiles; kb++) {
        const int k0 = kb * 64;
        // Stage K, V^T (hi/lo): 64x64 each
#pragma unroll
        for (int i = 0; i < 2; i++) {
            int idx = tid + i * 256;
            int r = idx >> 3, q = idx & 7;
            uint32_t so = r * SBFB + q * 16;
            size_t gk = ((size_t)bh * T_ + k0 + r) * CA_ + q * 8;
            size_t gv = ((size_t)bh * CA_ + r) * T_ + k0 + q * 8;
            *(uint4*)(sm + AOF_KH + so) = *(const uint4*)&g_kh[gk];
            *(uint4*)(sm + AOF_KL + so) = *(const uint4*)&g_kl[gk];
            *(uint4*)(sm + AOF_VH + so) = *(const uint4*)&g_vTh[gv];
            *(uint4*)(sm + AOF_VL + so) = *(const uint4*)&g_vTl[gv];
        }
        __syncthreads();

        // S = Q @ K^T (scale folded into Q)
        float DS[2][4][4];
#pragma unroll
        for (int a = 0; a < 2; a++)
#pragma unroll
            for (int b = 0; b < 4; b++)
#pragma unroll
                for (int c = 0; c < 4; c++) DS[a][b][c] = 0.f;
        mma_tile_k64(DS, smb + AOF_QH, smb + AOF_QL, smb + AOF_KH, smb + AOF_KL,
                     wm, wn, lane);

        // Write S fragments to smem
#pragma unroll
        for (int mi2 = 0; mi2 < 2; mi2++) {
            int r0 = wm * 32 + mi2 * 16 + (lane >> 2);
#pragma unroll
            for (int nf = 0; nf < 4; nf++) {
                int col = wn * 32 + nf * 8 + 2 * (lane & 3);
                S[(r0    ) * 65 + col    ] = DS[mi2][nf][0];
                S[(r0    ) * 65 + col + 1] = DS[mi2][nf][1];
                S[(r0 + 8) * 65 + col    ] = DS[mi2][nf][2];
                S[(r0 + 8) * 65 + col + 1] = DS[mi2][nf][3];
            }
        }
        __syncthreads();

        // Softmax: thread r < 128 owns query row r
        if (tid < 128) {
            const int r = tid;
            int jlim = 63;
            if (kb >= 2 * qt) {
                int lim = (q0 + r) - k0;
                jlim = lim < 63 ? lim : 63;
            }
            float mx = -1e30f;
            for (int j = 0; j <= jlim; j++) mx = fmaxf(mx, S[r * 65 + j]);
            float mnew = fmaxf(mi_s, mx);
            float cr = __expf(mi_s - mnew);
            float psum = 0.f;
#pragma unroll
            for (int j8 = 0; j8 < 8; j8++) {
                Pack8 hh, ll;
#pragma unroll
                for (int e = 0; e < 8; e++) {
                    int j = j8 * 8 + e;
                    float p = (j <= jlim) ? __expf(S[r * 65 + j] - mnew) : 0.f;
                    psum += p;
                    split2(p, hh.b[e], ll.b[e]);
                }
                *(uint4*)(sm + AOF_PH + r * SBFB + j8 * 16) = hh.u;
                *(uint4*)(sm + AOF_PL + r * SBFB + j8 * 16) = ll.u;
            }
            li = li * cr + psum;
            mi_s = mnew;
            corr_sm[r] = cr;
        }
        __syncthreads();

        // Rescale O by corr, then O += P @ V^T
#pragma unroll
        for (int mi2 = 0; mi2 < 2; mi2++) {
            int r0 = wm * 32 + mi2 * 16 + (lane >> 2);
            float c0 = corr_sm[r0], c1 = corr_sm[r0 + 8];
#pragma unroll
            for (int nf = 0; nf < 4; nf++) {
                DO[mi2][nf][0] *= c0; DO[mi2][nf][1] *= c0;
                DO[mi2][nf][2] *= c1; DO[mi2][nf][3] *= c1;
            }
        }
        mma_tile_k64(DO, smb + AOF_PH, smb + AOF_PL, smb + AOF_VH, smb + AOF_VL,
                     wm, wn, lane);
        __syncthreads();
    }

    // Epilogue: O / l -> y hi/lo
    if (tid < 128) corr_sm[tid] = 1.f / li;
    __syncthreads();

    const int bb = bh >> 4, h = bh & 15;
#pragma unroll
    for (int mi2 = 0; mi2 < 2; mi2++) {
        int r0 = wm * 32 + mi2 * 16 + (lane >> 2);
#pragma unroll
        for (int half = 0; half < 2; half++) {
            int row = r0 + half * 8;
            float inv = corr_sm[row];
            size_t rb = ((size_t)bb * T_ + q0 + row) * C_ + h * CA_;
#pragma unroll
            for (int nf = 0; nf < 4; nf++) {
                int col = wn * 32 + nf * 8 + 2 * (lane & 3);
                float v0 = DO[mi2][nf][half * 2 + 0] * inv;
                float v1 = DO[mi2][nf][half * 2 + 1] * inv;
                Pack2 ph, pl;
                split2(v0, ph.b[0], pl.b[0]);
                split2(v1, ph.b[1], pl.b[1]);
                *(uint32_t*)&g_yh[rb + col] = ph.u;
                *(uint32_t*)&g_yl[rb + col] = pl.u;
            }
        }
    }
}

// ---------------------------------------------------------------------------
// Output projection: out[m][n] = sum_c y[m][c] * wo[c][n]; grid (32, 16)
// ---------------------------------------------------------------------------
__global__ __launch_bounds__(256) void out_mma_kernel(float* __restrict__ out) {
    extern __shared__ char sm[];
    const uint32_t smb = smem_u32(sm);
    const int tid = threadIdx.x, lane = tid & 31, wid = tid >> 5;
    const int wm = wid >> 1, wn = wid & 1;
    const int m0 = blockIdx.x * 128;
    const int n0 = blockIdx.y * 64;

    float D[2][4][4];
#pragma unroll
    for (int a = 0; a < 2; a++)
#pragma unroll
        for (int b = 0; b < 4; b++)
#pragma unroll
            for (int c = 0; c < 4; c++) D[a][b][c] = 0.f;

    for (int ck = 0; ck < 16; ck++) {
        const int kt = ck * 64;
#pragma unroll
        for (int i = 0; i < 4; i++) {
            int idx = tid + i * 256;
            int r = idx >> 3, q = idx & 7;
            uint32_t so = r * SBFB + q * 16;
            size_t go = (size_t)(m0 + r) * C_ + kt + q * 8;
            *(uint4*)(sm + GOF_AH + so) = *(const uint4*)&g_yh[go];
            *(uint4*)(sm + GOF_AL + so) = *(const uint4*)&g_yl[go];
        }
#pragma unroll
        for (int i = 0; i < 2; i++) {
            int idx = tid + i * 256;
            int r = idx >> 3, q = idx & 7;
            uint32_t so = r * SBFB + q * 16;
            size_t go = (size_t)(n0 + r) * C_ + kt + q * 8;
            *(uint4*)(sm + GOF_BH + so) = *(const uint4*)&g_woTh[go];
            *(uint4*)(sm + GOF_BL + so) = *(const uint4*)&g_woTl[go];
        }
        __syncthreads();
        mma_tile_k64(D, smb + GOF_AH, smb + GOF_AL, smb + GOF_BH, smb + GOF_BL,
                     wm, wn, lane);
        __syncthreads();
    }

#pragma unroll
    for (int mi = 0; mi < 2; mi++) {
        int r0 = m0 + wm * 32 + mi * 16 + (lane >> 2);
#pragma unroll
        for (int half = 0; half < 2; half++) {
            int row = r0 + half * 8;
#pragma unroll
            for (int nf = 0; nf < 4; nf++) {
                int col = n0 + wn * 32 + nf * 8 + 2 * (lane & 3);
                float2 v = make_float2(D[mi][nf][half * 2 + 0], D[mi][nf][half * 2 + 1]);
                *(float2*)&out[(size_t)row * C_ + col] = v;
            }
        }
    }
}

// ---------------------------------------------------------------------------
extern "C" void kernel_launch(void* const* d_in, const int* in_sizes, int n_in,
                              void* d_out, int out_size) {
    const float* x   = (const float*)d_in[0];
    const float* w_q = (const float*)d_in[1];
    const float* w_k = (const float*)d_in[2];
    const float* w_v = (const float*)d_in[3];
    const float* w_o = (const float*)d_in[4];
    float* out = (float*)d_out;

    cudaFuncSetAttribute(qkv_mma_kernel, cudaFuncAttributeMaxDynamicSharedMemorySize, GEMM_SMEM);
    cudaFuncSetAttribute(attn_mma_kernel, cudaFuncAttributeMaxDynamicSharedMemorySize, ATT_SMEM);
    cudaFuncSetAttribute(out_mma_kernel, cudaFuncAttributeMaxDynamicSharedMemorySize, GEMM_SMEM);

    split_x_kernel<<<(M_TOT * C_) / (128 * 8), 128>>>(x);
    tsplit_kernel<<<dim3(16, 64), 128>>>(w_q, w_k, w_v, w_o);

    qkv_mma_kernel<<<dim3(M_TOT / 128, H_, 3), 256, GEMM_SMEM>>>();

    attn_mma_kernel<<<dim3(T_ / 128, BH_), 256, ATT_SMEM>>>();

    out_mma_kernel<<<dim3(M_TOT / 128, C_ / 64), 256, GEMM_SMEM>>>(out);
}

// round 7
// speedup vs baseline: 3.6321x; 1.2785x over previous
#include <cuda_runtime.h>
#include <cuda_bf16.h>
#include <math.h>
#include <stdint.h>

// Problem constants
#define B_  2
#define T_  2048
#define C_  1024
#define H_  16
#define CA_ 64
#define BH_ (B_*H_)
#define M_TOT (B_*T_)   // 4096

// ---------------------------------------------------------------------------
// bf16 hi/lo split scratch (device globals: allocation-guard safe)
// ---------------------------------------------------------------------------
__device__ __align__(128) __nv_bfloat16 g_xh[M_TOT*C_],  g_xl[M_TOT*C_];
__device__ __align__(128) __nv_bfloat16 g_wTh[3*H_*CA_*C_], g_wTl[3*H_*CA_*C_];
__device__ __align__(128) __nv_bfloat16 g_woTh[C_*C_],   g_woTl[C_*C_];
__device__ __align__(128) __nv_bfloat16 g_qh[BH_*T_*CA_], g_ql[BH_*T_*CA_];
__device__ __align__(128) __nv_bfloat16 g_kh[BH_*T_*CA_], g_kl[BH_*T_*CA_];
__device__ __align__(128) __nv_bfloat16 g_vTh[BH_*CA_*T_], g_vTl[BH_*CA_*T_];
__device__ __align__(128) __nv_bfloat16 g_yh[M_TOT*C_],  g_yl[M_TOT*C_];

// ---------------------------------------------------------------------------
// helpers
// ---------------------------------------------------------------------------
__device__ __forceinline__ uint32_t smem_u32(const void* p) {
    uint32_t a;
    asm("{ .reg .u64 t; cvta.to.shared.u64 t, %1; cvt.u32.u64 %0, t; }"
        : "=r"(a) : "l"(p));
    return a;
}

#define LDM_X4(regs, addr) \
    asm volatile("ldmatrix.sync.aligned.m8n8.x4.shared.b16 {%0,%1,%2,%3}, [%4];" \
        : "=r"((regs)[0]),"=r"((regs)[1]),"=r"((regs)[2]),"=r"((regs)[3]) : "r"(addr))

__device__ __forceinline__ void mma16816(float* d, const uint32_t* a, const uint32_t* b) {
    asm volatile("mma.sync.aligned.m16n8k16.row.col.f32.bf16.bf16.f32 "
        "{%0,%1,%2,%3}, {%4,%5,%6,%7}, {%8,%9}, {%0,%1,%2,%3};"
        : "+f"(d[0]),"+f"(d[1]),"+f"(d[2]),"+f"(d[3])
        : "r"(a[0]),"r"(a[1]),"r"(a[2]),"r"(a[3]), "r"(b[0]),"r"(b[1]));
}

__device__ __forceinline__ void split2(float v, __nv_bfloat16& h, __nv_bfloat16& l) {
    h = __float2bfloat16(v);
    l = __float2bfloat16(v - __bfloat162float(h));
}
union Pack8 { __nv_bfloat16 b[8]; uint4 u; };
union Pack2 { __nv_bfloat16 b[2]; uint32_t u; };

// split two floats into packed bf16x2 hi and lo words (elem0 in low 16 bits)
__device__ __forceinline__ void split_pack2(float x0, float x1,
                                            uint32_t& ph, uint32_t& pl) {
    __nv_bfloat16 h0, l0, h1, l1;
    split2(x0, h0, l0);
    split2(x1, h1, l1);
    Pack2 a; a.b[0] = h0; a.b[1] = h1; ph = a.u;
    Pack2 b; b.b[0] = l0; b.b[1] = l1; pl = b.u;
}

// cp.async 16B
__device__ __forceinline__ void cp16(uint32_t saddr, const void* g) {
    asm volatile("cp.async.cg.shared.global [%0], [%1], 16;" :: "r"(saddr), "l"(g));
}
#define CP_COMMIT() asm volatile("cp.async.commit_group;" ::: "memory")
#define CP_WAIT0()  asm volatile("cp.async.wait_group 0;" ::: "memory")

// bf16 tile row stride: 72 elems = 144 bytes (conflict-free for ldmatrix & STS)
#define SBF   72
#define SBFB  144

// ---------------------------------------------------------------------------
// Core warp-tile MMA over one K=64 chunk, 3-term hi/lo split. (GEMM kernels)
// Warp computes 32(M) x 32(N): D[2 mi][4 nf][4]
// ---------------------------------------------------------------------------
__device__ __forceinline__ void mma_tile_k64(
    float D[2][4][4],
    uint32_t aH, uint32_t aL, uint32_t bH, uint32_t bL,
    int warp_m, int warp_n, int lane)
{
    const uint32_t abyte = (uint32_t)(warp_m*32 + (lane & 15)) * SBFB + ((lane >> 4) * 16);
    const uint32_t bbyte = (uint32_t)(warp_n*32 + (lane & 7) + (((lane >> 4) & 1) * 8)) * SBFB
                         + (((lane >> 3) & 1) * 16);
#pragma unroll
    for (int ks = 0; ks < 4; ks++) {
        uint32_t ah[2][4], al[2][4], bh[2][4], bl[2][4];
#pragma unroll
        for (int mi = 0; mi < 2; mi++) {
            LDM_X4(ah[mi], aH + abyte + mi*16*SBFB + ks*32);
            LDM_X4(al[mi], aL + abyte + mi*16*SBFB + ks*32);
        }
#pragma unroll
        for (int np = 0; np < 2; np++) {
            LDM_X4(bh[np], bH + bbyte + np*16*SBFB + ks*32);
            LDM_X4(bl[np], bL + bbyte + np*16*SBFB + ks*32);
        }
#pragma unroll
        for (int mi = 0; mi < 2; mi++)
#pragma unroll
        for (int np = 0; np < 2; np++) {
            mma16816(D[mi][2*np],   ah[mi], &bh[np][0]);
            mma16816(D[mi][2*np],   ah[mi], &bl[np][0]);
            mma16816(D[mi][2*np],   al[mi], &bh[np][0]);
            mma16816(D[mi][2*np+1], ah[mi], &bh[np][2]);
            mma16816(D[mi][2*np+1], ah[mi], &bl[np][2]);
            mma16816(D[mi][2*np+1], al[mi], &bh[np][2]);
        }
    }
}

// ---------------------------------------------------------------------------
// Prep 1: elementwise split of x
// ---------------------------------------------------------------------------
__global__ __launch_bounds__(128) void split_x_kernel(const float* __restrict__ x) {
    size_t i8 = ((size_t)blockIdx.x * 128 + threadIdx.x) * 8;
    float4 v0 = *(const float4*)&x[i8];
    float4 v1 = *(const float4*)&x[i8 + 4];
    float v[8] = {v0.x, v0.y, v0.z, v0.w, v1.x, v1.y, v1.z, v1.w};
    Pack8 h, l;
#pragma unroll
    for (int e = 0; e < 8; e++) split2(v[e], h.b[e], l.b[e]);
    *(uint4*)&g_xh[i8] = h.u;
    *(uint4*)&g_xl[i8] = l.u;
}

// ---------------------------------------------------------------------------
// Prep 2: transpose + split weights.
// ---------------------------------------------------------------------------
__global__ __launch_bounds__(128) void tsplit_kernel(
    const float* __restrict__ wq, const float* __restrict__ wk,
    const float* __restrict__ wv, const float* __restrict__ wo) {
    __shared__ float ts[64 * 65];
    const int tid = threadIdx.x;
    const int c0  = blockIdx.x * 64;
    const int y   = blockIdx.y;

    const float* src; int sstride, coloff;
    __nv_bfloat16 *dsth, *dstl;
    if (y < 48) {
        int which = y >> 4, h = y & 15;
        const float* w = (which == 0) ? wq : (which == 1) ? wk : wv;
        src = w + (size_t)h * C_ * CA_;
        sstride = CA_; coloff = 0;
        dsth = g_wTh + (size_t)(which * H_ + h) * CA_ * C_;
        dstl = g_wTl + (size_t)(which * H_ + h) * CA_ * C_;
    } else {
        int nt = y - 48;
        src = wo; sstride = C_; coloff = nt * 64;
        dsth = g_woTh + (size_t)(nt * 64) * C_;
        dstl = g_woTl + (size_t)(nt * 64) * C_;
    }

#pragma unroll
    for (int i = 0; i < 8; i++) {
        int idx = tid + i * 128;
        int r = idx >> 4, q = idx & 15;
        float4 v = *(const float4*)&src[(size_t)(c0 + r) * sstride + coloff + q * 4];
        ts[r * 65 + q * 4 + 0] = v.x;
        ts[r * 65 + q * 4 + 1] = v.y;
        ts[r * 65 + q * 4 + 2] = v.z;
        ts[r * 65 + q * 4 + 3] = v.w;
    }
    __syncthreads();

#pragma unroll
    for (int i = 0; i < 4; i++) {
        int idx = tid + i * 128;
        int a = idx >> 3, c8 = idx & 7;
        Pack8 h, l;
#pragma unroll
        for (int j = 0; j < 8; j++)
            split2(ts[(c8 * 8 + j) * 65 + a], h.b[j], l.b[j]);
        size_t o = (size_t)a * C_ + c0 + c8 * 8;
        *(uint4*)&dsth[o] = h.u;
        *(uint4*)&dstl[o] = l.u;
    }
}

// ---------------------------------------------------------------------------
// smem layout for GEMM kernels (qkv / out-proj), K chunk = 64
// ---------------------------------------------------------------------------
#define GOF_AH 0
#define GOF_AL (128*SBFB)
#define GOF_BH (2*128*SBFB)
#define GOF_BL (2*128*SBFB + 64*SBFB)
#define GEMM_SMEM (2*128*SBFB + 2*64*SBFB)   // 55296

// ---------------------------------------------------------------------------
// QKV projection (unchanged from round 5)
// ---------------------------------------------------------------------------
__global__ __launch_bounds__(256) void qkv_mma_kernel() {
    extern __shared__ char sm[];
    const uint32_t smb = smem_u32(sm);
    const int tid = threadIdx.x, lane = tid & 31, wid = tid >> 5;
    const int wm = wid >> 1, wn = wid & 1;
    const int m0 = blockIdx.x * 128;
    const int h  = blockIdx.y;
    const int which = blockIdx.z;

    const __nv_bfloat16* bh_src = g_wTh + (size_t)(which * H_ + h) * CA_ * C_;
    const __nv_bfloat16* bl_src = g_wTl + (size_t)(which * H_ + h) * CA_ * C_;

    float D[2][4][4];
#pragma unroll
    for (int a = 0; a < 2; a++)
#pragma unroll
        for (int b = 0; b < 4; b++)
#pragma unroll
            for (int c = 0; c < 4; c++) D[a][b][c] = 0.f;

    for (int ck = 0; ck < 16; ck++) {
        const int kt = ck * 64;
#pragma unroll
        for (int i = 0; i < 4; i++) {
            int idx = tid + i * 256;
            int r = idx >> 3, q = idx & 7;
            uint32_t so = r * SBFB + q * 16;
            size_t go = (size_t)(m0 + r) * C_ + kt + q * 8;
            *(uint4*)(sm + GOF_AH + so) = *(const uint4*)&g_xh[go];
            *(uint4*)(sm + GOF_AL + so) = *(const uint4*)&g_xl[go];
        }
#pragma unroll
        for (int i = 0; i < 2; i++) {
            int idx = tid + i * 256;
            int r = idx >> 3, q = idx & 7;
            uint32_t so = r * SBFB + q * 16;
            size_t go = (size_t)r * C_ + kt + q * 8;
            *(uint4*)(sm + GOF_BH + so) = *(const uint4*)&bh_src[go];
            *(uint4*)(sm + GOF_BL + so) = *(const uint4*)&bl_src[go];
        }
        __syncthreads();
        mma_tile_k64(D, smb + GOF_AH, smb + GOF_AL, smb + GOF_BH, smb + GOF_BL,
                     wm, wn, lane);
        __syncthreads();
    }

    const int bb = m0 >> 11;
    const int m0t = m0 & (T_ - 1);

    if (which != 2) {
        const float sc = (which == 0) ? 0.125f : 1.0f;
        __nv_bfloat16* dh = (which == 0) ? g_qh : g_kh;
        __nv_bfloat16* dl = (which == 0) ? g_ql : g_kl;
        size_t hbase = (size_t)(bb * H_ + h) * T_ * CA_;
#pragma unroll
        for (int mi = 0; mi < 2; mi++) {
            int r0 = wm * 32 + mi * 16 + (lane >> 2);
#pragma unroll
            for (int half = 0; half < 2; half++) {
                int row = r0 + half * 8;
                size_t rb = hbase + (size_t)(m0t + row) * CA_;
#pragma unroll
                for (int nf = 0; nf < 4; nf++) {
                    int col = wn * 32 + nf * 8 + 2 * (lane & 3);
                    float v0 = D[mi][nf][half * 2 + 0] * sc;
                    float v1 = D[mi][nf][half * 2 + 1] * sc;
                    Pack2 ph, pl;
                    split2(v0, ph.b[0], pl.b[0]);
                    split2(v1, ph.b[1], pl.b[1]);
                    *(uint32_t*)&dh[rb + col] = ph.u;
                    *(uint32_t*)&dl[rb + col] = pl.u;
                }
            }
        }
    } else {
        float* Vs = (float*)sm;       // [128][68]
#pragma unroll
        for (int mi = 0; mi < 2; mi++) {
            int r0 = wm * 32 + mi * 16 + (lane >> 2);
#pragma unroll
            for (int nf = 0; nf < 4; nf++) {
                int col = wn * 32 + nf * 8 + 2 * (lane & 3);
                Vs[(r0    ) * 68 + col    ] = D[mi][nf][0];
                Vs[(r0    ) * 68 + col + 1] = D[mi][nf][1];
                Vs[(r0 + 8) * 68 + col    ] = D[mi][nf][2];
                Vs[(r0 + 8) * 68 + col + 1] = D[mi][nf][3];
            }
        }
        __syncthreads();
        const int a = tid & 63, part = tid >> 6;
        size_t base = ((size_t)(bb * H_ + h) * CA_ + a) * T_ + m0t + part * 32;
#pragma unroll
        for (int j8 = 0; j8 < 4; j8++) {
            Pack8 hh, ll;
#pragma unroll
            for (int e = 0; e < 8; e++)
                split2(Vs[(part * 32 + j8 * 8 + e) * 68 + a], hh.b[e], ll.b[e]);
            *(uint4*)&g_vTh[base + j8 * 8] = hh.u;
            *(uint4*)&g_vTl[base + j8 * 8] = ll.u;
        }
    }
}

// ---------------------------------------------------------------------------
// Flash attention v2: register-resident softmax, cp.async double buffering.
// 256 thr, 8 warps; warp w owns rows [16w,16w+16) x all 64 cols.
// Smem: 2 stages x (KH,KL,VH,VL) each 64x72 bf16 = 2x36864 = 73728 B.
// ---------------------------------------------------------------------------
#define KVB (64*SBFB)                 // 9216 per sub-buffer
#define STG (4*KVB)                   // 36864 per stage
#define ATT_SMEM (2*STG)              // 73728

__global__ __launch_bounds__(256, 2) void attn_mma_kernel() {
    extern __shared__ char sm[];
    const uint32_t smb = smem_u32(sm);
    const int tid = threadIdx.x, lane = tid & 31, wid = tid >> 5;
    const int qt = (int)gridDim.x - 1 - (int)blockIdx.x;   // long blocks first
    const int bh = blockIdx.y;
    const int q0 = qt * 128;

    const __nv_bfloat16* Kh = g_kh + (size_t)bh * T_ * CA_;
    const __nv_bfloat16* Kl = g_kl + (size_t)bh * T_ * CA_;
    const __nv_bfloat16* Vh = g_vTh + (size_t)bh * CA_ * T_;
    const __nv_bfloat16* Vl = g_vTl + (size_t)bh * CA_ * T_;

    // ---- Load Q into registers (stage via smem, then ldmatrix) ----
    uint32_t Qh[4][4], Ql[4][4];
    {
#pragma unroll
        for (int i = 0; i < 4; i++) {
            int idx = tid + i * 256;
            int r = idx >> 3, q = idx & 7;
            uint32_t so = r * SBFB + q * 16;
            size_t go = ((size_t)bh * T_ + q0 + r) * CA_ + q * 8;
            *(uint4*)(sm + so)         = *(const uint4*)&g_qh[go];
            *(uint4*)(sm + 18432 + so) = *(const uint4*)&g_ql[go];
        }
        __syncthreads();
        const uint32_t abyte = (uint32_t)(wid * 16 + (lane & 15)) * SBFB + ((lane >> 4) * 16);
#pragma unroll
        for (int ks = 0; ks < 4; ks++) {
            LDM_X4(Qh[ks], smb + abyte + ks * 32);
            LDM_X4(Ql[ks], smb + 18432 + abyte + ks * 32);
        }
        __syncthreads();
    }

    float DO[8][4];
#pragma unroll
    for (int a = 0; a < 8; a++)
#pragma unroll
        for (int c = 0; c < 4; c++) DO[a][c] = 0.f;
    float m_a = -1e30f, m_b = -1e30f, l_a = 0.f, l_b = 0.f;

    const int ktiles = 2 * qt + 2;
    const uint32_t bbyte = (uint32_t)((lane & 7) + (((lane >> 4) & 1) * 8)) * SBFB
                         + (((lane >> 3) & 1) * 16);
    const int rowA = q0 + wid * 16 + (lane >> 2);
    const int rowB = rowA + 8;
    const int colc = 2 * (lane & 3);

    // stage tile kb into buffer kb&1
    auto stage = [&](int kb) {
        const int k0 = kb * 64;
        const uint32_t sb = smb + (kb & 1) * STG;
#pragma unroll
        for (int i = 0; i < 2; i++) {
            int idx = tid + i * 256;
            int r = idx >> 3, q = idx & 7;
            uint32_t so = r * SBFB + q * 16;
            size_t gk = ((size_t)(k0 + r)) * CA_ + q * 8;
            size_t gv = ((size_t)r) * T_ + k0 + q * 8;
            cp16(sb +           so, Kh + gk);
            cp16(sb + KVB +     so, Kl + gk);
            cp16(sb + 2 * KVB + so, Vh + gv);
            cp16(sb + 3 * KVB + so, Vl + gv);
        }
        CP_COMMIT();
    };

    stage(0);
    for (int kb = 0; kb < ktiles; kb++) {
        const int k0 = kb * 64;
        const uint32_t sb = smb + (kb & 1) * STG;
        CP_WAIT0();
        __syncthreads();
        if (kb + 1 < ktiles) stage(kb + 1);

        // ---- S = Q @ K^T ----
        float DS[8][4];
#pragma unroll
        for (int a = 0; a < 8; a++)
#pragma unroll
            for (int c = 0; c < 4; c++) DS[a][c] = 0.f;
#pragma unroll
        for (int ks = 0; ks < 4; ks++) {
#pragma unroll
            for (int g = 0; g < 4; g++) {
                uint32_t bhf[4], blf[4];
                uint32_t ba = sb + bbyte + (uint32_t)g * 16 * SBFB + ks * 32;
                LDM_X4(bhf, ba);
                LDM_X4(blf, ba + KVB);
                mma16816(DS[2*g],   Qh[ks], &bhf[0]);
                mma16816(DS[2*g],   Qh[ks], &blf[0]);
                mma16816(DS[2*g],   Ql[ks], &bhf[0]);
                mma16816(DS[2*g+1], Qh[ks], &bhf[2]);
                mma16816(DS[2*g+1], Qh[ks], &blf[2]);
                mma16816(DS[2*g+1], Ql[ks], &bhf[2]);
            }
        }

        // ---- causal mask (register) ----
        if (kb >= 2 * qt) {
#pragma unroll
            for (int nf = 0; nf < 8; nf++) {
                int c0v = k0 + 8 * nf + colc;
                if (c0v     > rowA) DS[nf][0] = -1e30f;
                if (c0v + 1 > rowA) DS[nf][1] = -1e30f;
                if (c0v     > rowB) DS[nf][2] = -1e30f;
                if (c0v + 1 > rowB) DS[nf][3] = -1e30f;
            }
        }

        // ---- online softmax in registers ----
        float mA = -1e30f, mB = -1e30f;
#pragma unroll
        for (int nf = 0; nf < 8; nf++) {
            mA = fmaxf(mA, fmaxf(DS[nf][0], DS[nf][1]));
            mB = fmaxf(mB, fmaxf(DS[nf][2], DS[nf][3]));
        }
        mA = fmaxf(mA, __shfl_xor_sync(0xffffffffu, mA, 1));
        mA = fmaxf(mA, __shfl_xor_sync(0xffffffffu, mA, 2));
        mB = fmaxf(mB, __shfl_xor_sync(0xffffffffu, mB, 1));
        mB = fmaxf(mB, __shfl_xor_sync(0xffffffffu, mB, 2));
        float mnA = fmaxf(m_a, mA), mnB = fmaxf(m_b, mB);
        float crA = __expf(m_a - mnA), crB = __expf(m_b - mnB);
        float psA = 0.f, psB = 0.f;
#pragma unroll
        for (int nf = 0; nf < 8; nf++) {
            DS[nf][0] = __expf(DS[nf][0] - mnA);
            DS[nf][1] = __expf(DS[nf][1] - mnA);
            DS[nf][2] = __expf(DS[nf][2] - mnB);
            DS[nf][3] = __expf(DS[nf][3] - mnB);
            psA += DS[nf][0] + DS[nf][1];
            psB += DS[nf][2] + DS[nf][3];
        }
        psA += __shfl_xor_sync(0xffffffffu, psA, 1);
        psA += __shfl_xor_sync(0xffffffffu, psA, 2);
        psB += __shfl_xor_sync(0xffffffffu, psB, 1);
        psB += __shfl_xor_sync(0xffffffffu, psB, 2);
        l_a = l_a * crA + psA; m_a = mnA;
        l_b = l_b * crB + psB; m_b = mnB;

        // rescale O
#pragma unroll
        for (int nf = 0; nf < 8; nf++) {
            DO[nf][0] *= crA; DO[nf][1] *= crA;
            DO[nf][2] *= crB; DO[nf][3] *= crB;
        }

        // ---- O += P @ V^T (P from DS fragments, in-register) ----
#pragma unroll
        for (int ks2 = 0; ks2 < 4; ks2++) {
            uint32_t Pah[4], Pal[4];
            split_pack2(DS[2*ks2  ][0], DS[2*ks2  ][1], Pah[0], Pal[0]);
            split_pack2(DS[2*ks2  ][2], DS[2*ks2  ][3], Pah[1], Pal[1]);
            split_pack2(DS[2*ks2+1][0], DS[2*ks2+1][1], Pah[2], Pal[2]);
            split_pack2(DS[2*ks2+1][2], DS[2*ks2+1][3], Pah[3], Pal[3]);
#pragma unroll
            for (int g = 0; g < 4; g++) {
                uint32_t vhf[4], vlf[4];
                uint32_t ba = sb + 2 * KVB + bbyte + (uint32_t)g * 16 * SBFB + ks2 * 32;
                LDM_X4(vhf, ba);
                LDM_X4(vlf, ba + KVB);
                mma16816(DO[2*g],   Pah, &vhf[0]);
                mma16816(DO[2*g],   Pah, &vlf[0]);
                mma16816(DO[2*g],   Pal, &vhf[0]);
                mma16816(DO[2*g+1], Pah, &vhf[2]);
                mma16816(DO[2*g+1], Pah, &vlf[2]);
                mma16816(DO[2*g+1], Pal, &vhf[2]);
            }
        }
        __syncthreads();
    }

    // ---- Epilogue: O / l -> y hi/lo ----
    const float invA = 1.f / l_a, invB = 1.f / l_b;
    const int bb = bh >> 4, h = bh & 15;
    size_t rbA = ((size_t)bb * T_ + rowA) * C_ + h * CA_;
    size_t rbB = ((size_t)bb * T_ + rowB) * C_ + h * CA_;
#pragma unroll
    for (int nf = 0; nf < 8; nf++) {
        int col = 8 * nf + colc;
        Pack2 ph, pl;
        split2(DO[nf][0] * invA, ph.b[0], pl.b[0]);
        split2(DO[nf][1] * invA, ph.b[1], pl.b[1]);
        *(uint32_t*)&g_yh[rbA + col] = ph.u;
        *(uint32_t*)&g_yl[rbA + col] = pl.u;
        split2(DO[nf][2] * invB, ph.b[0], pl.b[0]);
        split2(DO[nf][3] * invB, ph.b[1], pl.b[1]);
        *(uint32_t*)&g_yh[rbB + col] = ph.u;
        *(uint32_t*)&g_yl[rbB + col] = pl.u;
    }
}

// ---------------------------------------------------------------------------
// Output projection (unchanged from round 5)
// ---------------------------------------------------------------------------
__global__ __launch_bounds__(256) void out_mma_kernel(float* __restrict__ out) {
    extern __shared__ char sm[];
    const uint32_t smb = smem_u32(sm);
    const int tid = threadIdx.x, lane = tid & 31, wid = tid >> 5;
    const int wm = wid >> 1, wn = wid & 1;
    const int m0 = blockIdx.x * 128;
    const int n0 = blockIdx.y * 64;

    float D[2][4][4];
#pragma unroll
    for (int a = 0; a < 2; a++)
#pragma unroll
        for (int b = 0; b < 4; b++)
#pragma unroll
            for (int c = 0; c < 4; c++) D[a][b][c] = 0.f;

    for (int ck = 0; ck < 16; ck++) {
        const int kt = ck * 64;
#pragma unroll
        for (int i = 0; i < 4; i++) {
            int idx = tid + i * 256;
            int r = idx >> 3, q = idx & 7;
            uint32_t so = r * SBFB + q * 16;
            size_t go = (size_t)(m0 + r) * C_ + kt + q * 8;
            *(uint4*)(sm + GOF_AH + so) = *(const uint4*)&g_yh[go];
            *(uint4*)(sm + GOF_AL + so) = *(const uint4*)&g_yl[go];
        }
#pragma unroll
        for (int i = 0; i < 2; i++) {
            int idx = tid + i * 256;
            int r = idx >> 3, q = idx & 7;
            uint32_t so = r * SBFB + q * 16;
            size_t go = (size_t)(n0 + r) * C_ + kt + q * 8;
            *(uint4*)(sm + GOF_BH + so) = *(const uint4*)&g_woTh[go];
            *(uint4*)(sm + GOF_BL + so) = *(const uint4*)&g_woTl[go];
        }
        __syncthreads();
        mma_tile_k64(D, smb + GOF_AH, smb + GOF_AL, smb + GOF_BH, smb + GOF_BL,
                     wm, wn, lane);
        __syncthreads();
    }

#pragma unroll
    for (int mi = 0; mi < 2; mi++) {
        int r0 = m0 + wm * 32 + mi * 16 + (lane >> 2);
#pragma unroll
        for (int half = 0; half < 2; half++) {
            int row = r0 + half * 8;
#pragma unroll
            for (int nf = 0; nf < 4; nf++) {
                int col = n0 + wn * 32 + nf * 8 + 2 * (lane & 3);
                float2 v = make_float2(D[mi][nf][half * 2 + 0], D[mi][nf][half * 2 + 1]);
                *(float2*)&out[(size_t)row * C_ + col] = v;
            }
        }
    }
}

// ---------------------------------------------------------------------------
extern "C" void kernel_launch(void* const* d_in, const int* in_sizes, int n_in,
                              void* d_out, int out_size) {
    const float* x   = (const float*)d_in[0];
    const float* w_q = (const float*)d_in[1];
    const float* w_k = (const float*)d_in[2];
    const float* w_v = (const float*)d_in[3];
    const float* w_o = (const float*)d_in[4];
    float* out = (float*)d_out;

    cudaFuncSetAttribute(qkv_mma_kernel, cudaFuncAttributeMaxDynamicSharedMemorySize, GEMM_SMEM);
    cudaFuncSetAttribute(attn_mma_kernel, cudaFuncAttributeMaxDynamicSharedMemorySize, ATT_SMEM);
    cudaFuncSetAttribute(out_mma_kernel, cudaFuncAttributeMaxDynamicSharedMemorySize, GEMM_SMEM);

    split_x_kernel<<<(M_TOT * C_) / (128 * 8), 128>>>(x);
    tsplit_kernel<<<dim3(16, 64), 128>>>(w_q, w_k, w_v, w_o);

    qkv_mma_kernel<<<dim3(M_TOT / 128, H_, 3), 256, GEMM_SMEM>>>();

    attn_mma_kernel<<<dim3(T_ / 128, BH_), 256, ATT_SMEM>>>();

    out_mma_kernel<<<dim3(M_TOT / 128, C_ / 64), 256, GEMM_SMEM>>>(out);
}